// round 14
// baseline (speedup 1.0000x reference)
#include <cuda_runtime.h>
#include <math.h>
#include <stdint.h>

typedef unsigned long long ull;

// Scratch: projected inputs [t][b][768] (xz cols 0..511 incl bias, xh cols 512..767)
__device__ float g_xzh[131072 * 768];  // 402 MB static scratch

// ---------------------------------------------------------------------------
// helpers
// ---------------------------------------------------------------------------
__device__ __forceinline__ ull dup2f(float x) {
    ull r; asm("mov.b64 %0, {%1, %1};" : "=l"(r) : "f"(x)); return r;
}
__device__ __forceinline__ void unpack2(ull v, float& x, float& y) {
    asm("mov.b64 {%0, %1}, %2;" : "=f"(x), "=f"(y) : "l"(v));
}
__device__ __forceinline__ void ffma2(ull& d, ull a, ull b) {
    asm("fma.rn.f32x2 %0, %1, %2, %0;" : "+l"(d) : "l"(a), "l"(b));
}
__device__ __forceinline__ uint32_t smem_u32(const void* p) {
    return (uint32_t)__cvta_generic_to_shared(p);
}
__device__ __forceinline__ uint32_t mapa_rank(uint32_t addr, uint32_t rank) {
    uint32_t r; asm("mapa.shared::cluster.u32 %0, %1, %2;" : "=r"(r) : "r"(addr), "r"(rank));
    return r;
}
__device__ __forceinline__ void st_cluster_f4(uint32_t addr, float4 v) {
    asm volatile("st.shared::cluster.v4.f32 [%0], {%1,%2,%3,%4};"
                 :: "r"(addr), "f"(v.x), "f"(v.y), "f"(v.z), "f"(v.w) : "memory");
}
__device__ __forceinline__ void cluster_sync_() {
    asm volatile("barrier.cluster.arrive.aligned;" ::: "memory");
    asm volatile("barrier.cluster.wait.aligned;" ::: "memory");
}
__device__ __forceinline__ float sigf(float x) {
    return __fdividef(1.f, 1.f + __expf(-x));
}
__device__ __forceinline__ float tanhfast(float x) {
    float a = fabsf(x);
    float e = __expf(2.f * a);
    float r = 1.f - __fdividef(2.f, e + 1.f);
    return copysignf(r, x);
}

// ---------------------------------------------------------------------------
// Kernel 1: projection GEMM, double-buffered (measured ~1.13 ms, kept).
// ---------------------------------------------------------------------------
__global__ __launch_bounds__(256, 2) void proj_gemm(
    const float* __restrict__ x,
    const float* __restrict__ Wzr,
    const float* __restrict__ Wh,
    const float* __restrict__ bzr,
    const float* __restrict__ bh)
{
    __shared__ float As[2][128][16];
    __shared__ float Bs[2][16][128];

    const int tid = threadIdx.x;
    const int tm = tid >> 4;
    const int tn = tid & 15;
    const int Mbase = blockIdx.y * 128;
    const int Nbase = blockIdx.x * 128;

    const bool isZr = (Nbase < 512);
    const float* __restrict__ W = isZr ? Wzr : Wh;
    const int ldw  = isZr ? 512 : 256;
    const int wcol = isZr ? Nbase : (Nbase - 512);

    ull acc2[8][4];
    #pragma unroll
    for (int i = 0; i < 8; i++)
        #pragma unroll
        for (int p = 0; p < 4; p++) acc2[i][p] = 0ull;

    const int ra = tid >> 2;
    const int ka = (tid & 3) << 2;
    const int rb = tid >> 5;
    const int nb = (tid & 31) << 2;

    float4 a0 = *(const float4*)&x[(size_t)(Mbase + ra)      * 256 + ka];
    float4 a1 = *(const float4*)&x[(size_t)(Mbase + ra + 64) * 256 + ka];
    float4 w0 = *(const float4*)&W[(size_t)(rb)     * ldw + wcol + nb];
    float4 w1 = *(const float4*)&W[(size_t)(rb + 8) * ldw + wcol + nb];
    *(float4*)&As[0][ra][ka]      = a0;
    *(float4*)&As[0][ra + 64][ka] = a1;
    *(float4*)&Bs[0][rb][nb]      = w0;
    *(float4*)&Bs[0][rb + 8][nb]  = w1;
    __syncthreads();

    int cur = 0;
    for (int kt = 16; kt <= 256; kt += 16) {
        if (kt < 256) {
            a0 = *(const float4*)&x[(size_t)(Mbase + ra)      * 256 + kt + ka];
            a1 = *(const float4*)&x[(size_t)(Mbase + ra + 64) * 256 + kt + ka];
            w0 = *(const float4*)&W[(size_t)(kt + rb)     * ldw + wcol + nb];
            w1 = *(const float4*)&W[(size_t)(kt + rb + 8) * ldw + wcol + nb];
        }
        #pragma unroll
        for (int kk = 0; kk < 16; kk++) {
            ulonglong2 b01 = *(const ulonglong2*)&Bs[cur][kk][tn * 8];
            ulonglong2 b23 = *(const ulonglong2*)&Bs[cur][kk][tn * 8 + 4];
            #pragma unroll
            for (int i = 0; i < 8; i++) {
                ull ad = dup2f(As[cur][tm * 8 + i][kk]);
                ffma2(acc2[i][0], ad, b01.x);
                ffma2(acc2[i][1], ad, b01.y);
                ffma2(acc2[i][2], ad, b23.x);
                ffma2(acc2[i][3], ad, b23.y);
            }
        }
        if (kt < 256) {
            int nxt = cur ^ 1;
            *(float4*)&As[nxt][ra][ka]      = a0;
            *(float4*)&As[nxt][ra + 64][ka] = a1;
            *(float4*)&Bs[nxt][rb][nb]      = w0;
            *(float4*)&Bs[nxt][rb + 8][nb]  = w1;
            __syncthreads();
            cur = nxt;
        }
    }

    float bias[8];
    #pragma unroll
    for (int jj = 0; jj < 8; jj++) {
        int c = Nbase + tn * 8 + jj;
        bias[jj] = (c < 512) ? bzr[c] : bh[c - 512];
    }

    #pragma unroll
    for (int i = 0; i < 8; i++) {
        int r = Mbase + tm * 8 + i;   // r = b*1024 + t
        int b = r >> 10;
        int t = r & 1023;
        float* dst = &g_xzh[(size_t)((t << 7) + b) * 768 + Nbase + tn * 8];
        float c[8];
        #pragma unroll
        for (int p = 0; p < 4; p++) unpack2(acc2[i][p], c[2 * p], c[2 * p + 1]);
        float4 v0, v1;
        v0.x = c[0] + bias[0]; v0.y = c[1] + bias[1];
        v0.z = c[2] + bias[2]; v0.w = c[3] + bias[3];
        v1.x = c[4] + bias[4]; v1.y = c[5] + bias[5];
        v1.z = c[6] + bias[6]; v1.w = c[7] + bias[7];
        *(float4*)dst       = v0;
        *(float4*)(dst + 4) = v1;
    }
}

// ---------------------------------------------------------------------------
// Kernel 2: GRU recurrence. 32 clusters x 4 CTAs x 256 threads, register-
// resident weights, cluster.sync (R9 skeleton). Changes vs R9:
//  (a) INTERLEAVED gate ownership: CTA r computes Z-cols [64r,64r+64) and
//      R-cols [256+64r,+64). Z routing becomes a LOCAL store (no DSMEM);
//      every CTA broadcasts exactly 64 R*h cols -> DSMEM balanced, max/CTA
//      drops 8KB+2KB -> 4KB.
//  (b) k-split 4 (not 8): thread = (ks 0..3, u 0..63) owns 2 z-cols, 64 k.
//      Same 192 weight regs, same FMA count, reduce depth 8 -> 4.
// ---------------------------------------------------------------------------
extern "C" __global__ void __launch_bounds__(256, 1) __cluster_dims__(4, 1, 1)
gru_recur_bal(const float* __restrict__ Uzr,
              const float* __restrict__ Uh,
              float* __restrict__ out)
{
    __shared__ float4 red4[4 * 128];   // 8 KB partials (phase2 uses [4][64])
    __shared__ float4 h4[256];         // h, rows 0..3 per hidden col
    __shared__ float4 rh4[256];        // R*h, all 256 hidden cols
    __shared__ float4 z4[64];          // Z for this CTA's S cols (LOCAL only)

    const int tid  = threadIdx.x;
    const int ks   = tid >> 6;        // k-slice: k in [64ks, 64ks+64)
    const int u    = tid & 63;        // column unit (2 cols)
    const uint32_t crank = blockIdx.x & 3;
    const int r0 = (blockIdx.x >> 2) * 4;   // first batch row of this cluster

    // ---- prologue: weight slices -> REGISTERS, h = 0 ----
    // phase1 cols (local lc = 2u, 2u+1):
    //   u < 32  -> Z-type, global col g0 = 64*crank + 2u
    //   u >= 32 -> R-type, global col g0 = 256 + 64*crank + 2(u-32)
    float wz[64][2];
    float wh[64];
    {
        const int g0 = (u < 32) ? (int)(64 * crank + 2 * u)
                                : (int)(256 + 64 * crank + 2 * (u - 32));
        const float* pz = Uzr + (size_t)(ks * 64) * 512 + g0;
        #pragma unroll
        for (int kk = 0; kk < 64; kk++)
            *(float2*)wz[kk] = *(const float2*)(pz + (size_t)kk * 512);
        const float* ph = Uh + (size_t)(ks * 64) * 256 + 64 * crank + u;
        #pragma unroll
        for (int kk = 0; kk < 64; kk++)
            wh[kk] = ph[(size_t)kk * 256];
    }
    h4[tid] = make_float4(0.f, 0.f, 0.f, 0.f);
    __syncthreads();
    cluster_sync_();

    // DSMEM peer addresses (rh and h broadcast only; Z is local now)
    uint32_t h_base = smem_u32(h4), rh_base = smem_u32(rh4);
    uint32_t h_r[4], rh_r[4];
    #pragma unroll
    for (uint32_t r = 0; r < 4; r++) {
        h_r[r]  = mapa_rank(h_base, r);
        rh_r[r] = mapa_rank(rh_base, r);
    }

    const ull* h_u  = (const ull*)h4;
    const ull* rh_u = (const ull*)rh4;

    #pragma unroll 1
    for (int t = 0; t < 1024; t++) {
        // ---- prefetch this step's xz / xh (DRAM; consumed at the reduces) ----
        const size_t tb = (size_t)((t << 7) + r0) * 768;
        float xz0 = 0.f, xz1 = 0.f, xz2 = 0.f, xz3 = 0.f;
        float xh0 = 0.f, xh1 = 0.f, xh2 = 0.f, xh3 = 0.f;
        if (tid < 128) {
            // interleaved gate cols: tid<64 -> Z col 64c+tid ; else R col 256+64c+(tid-64)
            int gcol = (tid < 64) ? (int)(64 * crank + tid)
                                  : (int)(256 + 64 * crank + (tid - 64));
            const float* p = g_xzh + tb + gcol;
            xz0 = p[0]; xz1 = p[768]; xz2 = p[1536]; xz3 = p[2304];
        }
        if (tid < 64) {
            const float* p = g_xzh + tb + 512 + 64 * crank + tid;
            xh0 = p[0]; xh1 = p[768]; xh2 = p[1536]; xh3 = p[2304];
        }

        // ---- phase 1: partial z[4 rows][2 cols/thread], k in [64ks, 64ks+64) ----
        ull a01[2] = {0, 0}, a23[2] = {0, 0};
        {
            const ull* hp = h_u + ks * 128;      // 64 k * 2 ull
            #pragma unroll
            for (int kk = 0; kk < 64; kk++) {
                ulonglong2 hv = *(const ulonglong2*)(hp + 2 * kk);  // rows (0,1),(2,3)
                ull w0 = dup2f(wz[kk][0]), w1 = dup2f(wz[kk][1]);
                ffma2(a01[0], w0, hv.x); ffma2(a23[0], w0, hv.y);
                ffma2(a01[1], w1, hv.x); ffma2(a23[1], w1, hv.y);
            }
        }
        // store partials: layout [ks][slot], slot(col) = (col>>1) + (col&1)*64
        // col 2u -> slot u ; col 2u+1 -> slot u+64  (16B lane stride, no conflicts)
        {
            ulonglong2 v0; v0.x = a01[0]; v0.y = a23[0];
            ulonglong2 v1; v1.x = a01[1]; v1.y = a23[1];
            *(ulonglong2*)&red4[ks * 128 + u]      = v0;
            *(ulonglong2*)&red4[ks * 128 + u + 64] = v1;
        }
        __syncthreads();

        // ---- reduce1 + gates + routing (tid < 128, col = tid) ----
        if (tid < 128) {
            int slot = (tid >> 1) + (tid & 1) * 64;
            float4 s = red4[slot];
            #pragma unroll
            for (int w = 1; w < 4; w++) {
                float4 p = red4[w * 128 + slot];
                s.x += p.x; s.y += p.y; s.z += p.z; s.w += p.w;
            }
            s.x += xz0; s.y += xz1; s.z += xz2; s.w += xz3;
            float4 g;
            g.x = sigf(s.x); g.y = sigf(s.y); g.z = sigf(s.z); g.w = sigf(s.w);
            if (tid < 64) {
                // Z gate for S col 64*crank+tid -> owned by THIS CTA: local store
                z4[tid] = g;
            } else {
                // R gate: rh = R .* h for hidden col 64*crank + (tid-64);
                // broadcast to all 4 CTAs (4 KB per CTA, balanced)
                int ch = 64 * (int)crank + (tid - 64);
                float4 hv = h4[ch];
                float4 rh;
                rh.x = g.x * hv.x; rh.y = g.y * hv.y;
                rh.z = g.z * hv.z; rh.w = g.w * hv.w;
                uint32_t off = (uint32_t)ch * 16;
                #pragma unroll
                for (uint32_t r = 0; r < 4; r++)
                    st_cluster_f4(rh_r[r] + off, rh);
            }
        }
        cluster_sync_();

        // ---- phase 2: partial S[4 rows][1 col/thread], k in [64ks, 64ks+64) ----
        ull b01 = 0, b23 = 0;
        {
            const ull* rp = rh_u + ks * 128;
            #pragma unroll
            for (int kk = 0; kk < 64; kk++) {
                ulonglong2 rv = *(const ulonglong2*)(rp + 2 * kk);
                ull wd = dup2f(wh[kk]);
                ffma2(b01, wd, rv.x); ffma2(b23, wd, rv.y);
            }
        }
        {
            ulonglong2 v; v.x = b01; v.y = b23;
            *(ulonglong2*)&red4[ks * 64 + u] = v;    // 16B lane stride, no conflicts
        }
        __syncthreads();

        // ---- reduce2 + combine + h broadcast (tid < 64, col = tid) ----
        if (tid < 64) {
            float4 s = red4[tid];
            #pragma unroll
            for (int w = 1; w < 4; w++) {
                float4 p = red4[w * 64 + tid];
                s.x += p.x; s.y += p.y; s.z += p.z; s.w += p.w;
            }
            float S0 = tanhfast(s.x + xh0), S1 = tanhfast(s.y + xh1);
            float S2 = tanhfast(s.z + xh2), S3 = tanhfast(s.w + xh3);
            float4 Z = z4[tid];
            int gcol = (int)crank * 64 + tid;
            float4 hv = h4[gcol];
            float4 hn;
            hn.x = fmaf(Z.x, S0 - hv.x, hv.x);
            hn.y = fmaf(Z.y, S1 - hv.y, hv.y);
            hn.z = fmaf(Z.z, S2 - hv.z, hv.z);
            hn.w = fmaf(Z.w, S3 - hv.w, hv.w);
            uint32_t off = (uint32_t)gcol * 16;
            #pragma unroll
            for (uint32_t r = 0; r < 4; r++)
                st_cluster_f4(h_r[r] + off, hn);
        }
        cluster_sync_();
    }

    // ---- epilogue: rank 0 writes the 4 rows ----
    if (crank == 0) {
        float4 hv = h4[tid];
        out[(r0 + 0) * 256 + tid] = hv.x;
        out[(r0 + 1) * 256 + tid] = hv.y;
        out[(r0 + 2) * 256 + tid] = hv.z;
        out[(r0 + 3) * 256 + tid] = hv.w;
    }
}

// ---------------------------------------------------------------------------
extern "C" void kernel_launch(void* const* d_in, const int* in_sizes, int n_in,
                              void* d_out, int out_size)
{
    (void)in_sizes; (void)n_in; (void)out_size;
    const float* x   = (const float*)d_in[0];
    const float* Wzr = (const float*)d_in[1];
    const float* Uzr = (const float*)d_in[2];
    const float* bzr = (const float*)d_in[3];
    const float* Wh  = (const float*)d_in[4];
    const float* Uh  = (const float*)d_in[5];
    const float* bh  = (const float*)d_in[6];

    dim3 ggrid(6, 1024);
    proj_gemm<<<ggrid, 256>>>(x, Wzr, Wh, bzr, bh);

    gru_recur_bal<<<128, 256>>>(Uzr, Uh, (float*)d_out);
}